// round 11
// baseline (speedup 1.0000x reference)
#include <cuda_runtime.h>
#include <cuda_bf16.h>
#include <cstdint>
#include <cstddef>

#define NB   16
#define CIN  256
#define WD   128
#define SP   4096
#define KVS  16
#define EPSN 1e-5f
#define KC   32     // k-chunk in floats
#define ROWW 36     // SMEM words/row: 16 hi + 16 lo + 4 pad

// ---------------- scratch ----------------
__device__ float g_thetaT[(size_t)NB * SP * WD];
__device__ float g_phi   [(size_t)NB * WD * SP];
__device__ float g_gm    [(size_t)NB * WD * SP];
__device__ float g_kvp   [(size_t)NB * KVS * WD * WD];
__device__ float g_kvT   [(size_t)NB * WD * WD];
__device__ float g_y     [(size_t)NB * SP * WD];

#define MMA_BF16(d, a0,a1,a2,a3, b0,b1) \
    asm volatile("mma.sync.aligned.m16n8k16.row.col.f32.bf16.bf16.f32 " \
        "{%0,%1,%2,%3}, {%4,%5,%6,%7}, {%8,%9}, {%0,%1,%2,%3};" \
        : "+f"((d)[0]), "+f"((d)[1]), "+f"((d)[2]), "+f"((d)[3]) \
        : "r"(a0), "r"(a1), "r"(a2), "r"(a3), "r"(b0), "r"(b1))

__device__ __forceinline__ void cvt_hl(float a, float b, uint32_t& hi, uint32_t& lo) {
    __nv_bfloat16 ha = __float2bfloat16_rn(a), hb = __float2bfloat16_rn(b);
    float fa = __bfloat162float(ha), fb = __bfloat162float(hb);
    __nv_bfloat16 la = __float2bfloat16_rn(a - fa), lb = __float2bfloat16_rn(b - fb);
    __nv_bfloat162 h; h.x = ha; h.y = hb;
    __nv_bfloat162 l; l.x = la; l.y = lb;
    hi = *reinterpret_cast<uint32_t*>(&h);
    lo = *reinterpret_cast<uint32_t*>(&l);
}

// K-major source: 128 rows (m) x 32 floats (k), row stride ldk
__device__ __forceinline__ void load_conv(uint32_t* sm, const float* __restrict__ src,
                                          int ldk, int tid) {
#pragma unroll
    for (int i = 0; i < 4; i++) {
        int f = tid + (i << 8);
        int row = f >> 3, c = f & 7;
        float4 v = *(const float4*)(src + (size_t)row * ldk + (c << 2));
        uint32_t h0, l0, h1, l1;
        cvt_hl(v.x, v.y, h0, l0);
        cvt_hl(v.z, v.w, h1, l1);
        uint32_t* p = sm + row * ROWW + c * 2;
        p[0] = h0; p[1] = h1;
        p[16] = l0; p[17] = l1;
    }
}

// M-major (transposed) source: 32 rows (k) x 128 floats (m), row stride ldm.
// Transposes into the same [m-row][k-word] hi/lo SMEM layout as load_conv.
__device__ __forceinline__ void load_conv_T(uint32_t* sm, const float* __restrict__ src,
                                            int ldm, int tid) {
#pragma unroll
    for (int i = 0; i < 2; i++) {
        int u = tid + (i << 8);          // 0..511
        int kp = u >> 5, m4 = u & 31;    // k word 0..15, m-quad 0..31
        const float* p0 = src + (size_t)(2 * kp) * ldm + (m4 << 2);
        float4 v0 = *(const float4*)p0;
        float4 v1 = *(const float4*)(p0 + ldm);
        uint32_t h, l;
        uint32_t* q = sm + (m4 << 2) * ROWW + kp;
        cvt_hl(v0.x, v1.x, h, l); q[0]          = h; q[16]           = l;
        cvt_hl(v0.y, v1.y, h, l); q[ROWW]       = h; q[ROWW + 16]    = l;
        cvt_hl(v0.z, v1.z, h, l); q[2 * ROWW]   = h; q[2 * ROWW + 16] = l;
        cvt_hl(v0.w, v1.w, h, l); q[3 * ROWW]   = h; q[3 * ROWW + 16] = l;
    }
}

// D[128][128] = A[128][K] . B[128][K]^T, 3-product bf16 error compensation.
// TA/TB: operand source is [k][m] (transposed in SMEM loader).
template<bool TA, bool TB>
__device__ __forceinline__ void gemm_main(const float* __restrict__ A, int lda,
                                          const float* __restrict__ B, int ldb,
                                          int nchunk, float acc[4][4][4]) {
    __shared__ uint32_t smA[128 * ROWW];
    __shared__ uint32_t smB[128 * ROWW];
    const int tid = threadIdx.x, lane = tid & 31, wid = tid >> 5;
    const int wr = wid >> 2, wc = wid & 3;
    const int r = lane >> 2, q = lane & 3;
#pragma unroll
    for (int mi = 0; mi < 4; mi++)
#pragma unroll
        for (int ni = 0; ni < 4; ni++)
#pragma unroll
            for (int k = 0; k < 4; k++) acc[mi][ni][k] = 0.f;

    for (int kc = 0; kc < nchunk; kc++) {
        if (TA) load_conv_T(smA, A + (size_t)kc * KC * lda, lda, tid);
        else    load_conv  (smA, A + kc * KC, lda, tid);
        if (TB) load_conv_T(smB, B + (size_t)kc * KC * ldb, ldb, tid);
        else    load_conv  (smB, B + kc * KC, ldb, tid);
        __syncthreads();
#pragma unroll
        for (int p = 0; p < 3; p++) {
            const int aoff = (p == 1) ? 16 : 0;
            const int boff = (p == 2) ? 16 : 0;
#pragma unroll
            for (int k2 = 0; k2 < 2; k2++) {
                const int kwA = aoff + k2 * 8, kwB = boff + k2 * 8;
                uint32_t bf[4][2];
#pragma unroll
                for (int ni = 0; ni < 4; ni++) {
                    int nr = wc * 32 + ni * 8 + r;
                    bf[ni][0] = smB[nr * ROWW + kwB + q];
                    bf[ni][1] = smB[nr * ROWW + kwB + 4 + q];
                }
#pragma unroll
                for (int mi = 0; mi < 4; mi++) {
                    int mr = wr * 64 + mi * 16 + r;
                    uint32_t a0 = smA[mr * ROWW + kwA + q];
                    uint32_t a1 = smA[(mr + 8) * ROWW + kwA + q];
                    uint32_t a2 = smA[mr * ROWW + kwA + 4 + q];
                    uint32_t a3 = smA[(mr + 8) * ROWW + kwA + 4 + q];
#pragma unroll
                    for (int ni = 0; ni < 4; ni++)
                        MMA_BF16(acc[mi][ni], a0, a1, a2, a3, bf[ni][0], bf[ni][1]);
                }
            }
        }
        __syncthreads();
    }
}

// ---------------- GEMM 1: theta/phi/g ----------------
// grid (3, SP/128, NB): proj fastest -> x tile L2 reuse across projs
__global__ __launch_bounds__(256, 2) void qkv_tc(
    const float* __restrict__ x,
    const float* __restrict__ w0, const float* __restrict__ w1, const float* __restrict__ w2,
    const float* __restrict__ g1, const float* __restrict__ b1, const float* __restrict__ m1, const float* __restrict__ v1,
    const float* __restrict__ g2, const float* __restrict__ b2, const float* __restrict__ m2, const float* __restrict__ v2,
    const float* __restrict__ g3, const float* __restrict__ b3, const float* __restrict__ m3, const float* __restrict__ v3)
{
    const int proj = blockIdx.x, n = blockIdx.z, s0 = blockIdx.y * 128;
    const float* w = (proj == 0) ? w0 : (proj == 1) ? w1 : w2;
    const float* xsrc = x + (size_t)n * CIN * SP + s0;   // element (k=0, m=s0), row stride SP
    float acc[4][4][4];
    if (proj == 0) gemm_main<true,  false>(xsrc, SP, w, CIN, CIN / KC, acc);  // D[s][c']
    else           gemm_main<false, true >(w, CIN, xsrc, SP, CIN / KC, acc);  // D[c'][s]

    const int lane = threadIdx.x & 31, wid = threadIdx.x >> 5;
    const int wr = wid >> 2, wc = wid & 3, r = lane >> 2, q = lane & 3;

    if (proj == 0) {    // BN per column c'
#pragma unroll
        for (int mi = 0; mi < 4; mi++) {
            int sr = wr * 64 + mi * 16 + r;
            float* d0 = g_thetaT + ((size_t)n * SP + s0 + sr) * WD;
            float* d1 = d0 + (size_t)8 * WD;
#pragma unroll
            for (int ni = 0; ni < 4; ni++) {
                int col = wc * 32 + ni * 8 + q * 2;
                float sa = g1[col] * rsqrtf(v1[col] + EPSN);
                float ha = b1[col] - m1[col] * sa;
                float sb = g1[col + 1] * rsqrtf(v1[col + 1] + EPSN);
                float hb = b1[col + 1] - m1[col + 1] * sb;
                float2 u, v2_;
                u.x   = fmaxf(fmaf(acc[mi][ni][0], sa, ha), 0.f);
                u.y   = fmaxf(fmaf(acc[mi][ni][1], sb, hb), 0.f);
                v2_.x = fmaxf(fmaf(acc[mi][ni][2], sa, ha), 0.f);
                v2_.y = fmaxf(fmaf(acc[mi][ni][3], sb, hb), 0.f);
                *(float2*)(d0 + col) = u;
                *(float2*)(d1 + col) = v2_;
            }
        }
    } else {            // BN per row c'
        const float* bg = (proj == 1) ? g2 : g3; const float* bb = (proj == 1) ? b2 : b3;
        const float* bm = (proj == 1) ? m2 : m3; const float* bv = (proj == 1) ? v2 : v3;
        float* dst = (proj == 1) ? g_phi : g_gm;
#pragma unroll
        for (int mi = 0; mi < 4; mi++) {
            int c0r = wr * 64 + mi * 16 + r, c1r = c0r + 8;
            float sA = bg[c0r] * rsqrtf(bv[c0r] + EPSN), hA = bb[c0r] - bm[c0r] * sA;
            float sB = bg[c1r] * rsqrtf(bv[c1r] + EPSN), hB = bb[c1r] - bm[c1r] * sB;
            float* p0 = dst + ((size_t)n * WD + c0r) * SP + s0;
            float* p1 = dst + ((size_t)n * WD + c1r) * SP + s0;
#pragma unroll
            for (int ni = 0; ni < 4; ni++) {
                int col = wc * 32 + ni * 8 + q * 2;
                float2 u, v2_;
                u.x   = fmaxf(fmaf(acc[mi][ni][0], sA, hA), 0.f);
                u.y   = fmaxf(fmaf(acc[mi][ni][1], sA, hA), 0.f);
                v2_.x = fmaxf(fmaf(acc[mi][ni][2], sB, hB), 0.f);
                v2_.y = fmaxf(fmaf(acc[mi][ni][3], sB, hB), 0.f);
                *(float2*)(p0 + col) = u;
                *(float2*)(p1 + col) = v2_;
            }
        }
    }
}

// ---------------- GEMM 2: kv partials (D[d][c]) ---------------- grid (KVS, NB)
__global__ __launch_bounds__(256, 2) void kv_tc()
{
    const int n = blockIdx.y, s0 = blockIdx.x * (SP / KVS);
    const float* gsrc = g_gm  + (size_t)n * WD * SP + s0;
    const float* psrc = g_phi + (size_t)n * WD * SP + s0;
    float acc[4][4][4];
    gemm_main<false, false>(gsrc, SP, psrc, SP, (SP / KVS) / KC, acc);

    const int lane = threadIdx.x & 31, wid = threadIdx.x >> 5;
    const int wr = wid >> 2, wc = wid & 3, r = lane >> 2, q = lane & 3;
    float* base = g_kvp + ((size_t)n * KVS + blockIdx.x) * WD * WD;
#pragma unroll
    for (int mi = 0; mi < 4; mi++) {
        int dr = wr * 64 + mi * 16 + r;
        float* p0 = base + (size_t)dr * WD;
        float* p1 = p0 + (size_t)8 * WD;
#pragma unroll
        for (int ni = 0; ni < 4; ni++) {
            int col = wc * 32 + ni * 8 + q * 2;
            *(float2*)(p0 + col) = make_float2(acc[mi][ni][0], acc[mi][ni][1]);
            *(float2*)(p1 + col) = make_float2(acc[mi][ni][2], acc[mi][ni][3]);
        }
    }
}
__global__ __launch_bounds__(256) void kv_reduce()
{
    int idx = blockIdx.x * 256 + threadIdx.x;
    int n = idx >> 14, dc = idx & 16383;
    float s = 0.f;
#pragma unroll
    for (int k = 0; k < KVS; k++) s += g_kvp[(((size_t)n * KVS + k) << 14) + dc];
    g_kvT[idx] = s;
}

// ---------------- GEMM 3: y_flat (D[s][d]) ---------------- grid (SP/128, NB)
__global__ __launch_bounds__(256, 2) void outc_tc()
{
    const int n = blockIdx.y, s0 = blockIdx.x * 128;
    const float* tsrc = g_thetaT + ((size_t)n * SP + s0) * WD;
    const float* ksrc = g_kvT + (size_t)n * WD * WD;
    float acc[4][4][4];
    gemm_main<false, false>(tsrc, WD, ksrc, WD, WD / KC, acc);

    const int lane = threadIdx.x & 31, wid = threadIdx.x >> 5;
    const int wr = wid >> 2, wc = wid & 3, r = lane >> 2, q = lane & 3;
#pragma unroll
    for (int mi = 0; mi < 4; mi++) {
        int sr = wr * 64 + mi * 16 + r;
        float* p0 = g_y + ((size_t)n * SP + s0 + sr) * WD;
        float* p1 = p0 + (size_t)8 * WD;
#pragma unroll
        for (int ni = 0; ni < 4; ni++) {
            int col = wc * 32 + ni * 8 + q * 2;
            *(float2*)(p0 + col) = make_float2(acc[mi][ni][0], acc[mi][ni][1]);
            *(float2*)(p1 + col) = make_float2(acc[mi][ni][2], acc[mi][ni][3]);
        }
    }
}

// ---------------- GEMM 4: zeta + BN4 + residual + relu (D[o][s]) ----------------
// grid (CIN/128, SP/128, NB): o-tile fastest -> y tile L2 reuse.
// B operand: y viewed as [w][sp] (flat w*4096+sp), rows contiguous in sp -> transposed loader.
__global__ __launch_bounds__(256, 2) void zeta_tc(
    const float* __restrict__ x, const float* __restrict__ wz,
    const float* __restrict__ g4, const float* __restrict__ b4,
    const float* __restrict__ m4, const float* __restrict__ v4,
    float* __restrict__ out)
{
    const int n = blockIdx.z, o0 = blockIdx.x * 128, s0 = blockIdx.y * 128;
    const float* wsrc = wz + (size_t)o0 * WD;
    const float* ysrc = g_y + (size_t)n * SP * WD + s0;   // element (k=w=0, m=sp=s0), row stride SP
    float acc[4][4][4];
    gemm_main<false, true>(wsrc, WD, ysrc, SP, WD / KC, acc);

    const int lane = threadIdx.x & 31, wid = threadIdx.x >> 5;
    const int wr = wid >> 2, wc = wid & 3, r = lane >> 2, q = lane & 3;
#pragma unroll
    for (int mi = 0; mi < 4; mi++) {
        int oA = o0 + wr * 64 + mi * 16 + r, oB = oA + 8;
        float sA = g4[oA] * rsqrtf(v4[oA] + EPSN), hA = b4[oA] - m4[oA] * sA;
        float sB = g4[oB] * rsqrtf(v4[oB] + EPSN), hB = b4[oB] - m4[oB] * sB;
        const float* x0 = x + ((size_t)n * CIN + oA) * SP + s0;
        const float* x1 = x + ((size_t)n * CIN + oB) * SP + s0;
        float* p0 = out + ((size_t)n * CIN + oA) * SP + s0;
        float* p1 = out + ((size_t)n * CIN + oB) * SP + s0;
#pragma unroll
        for (int ni = 0; ni < 4; ni++) {
            int col = wc * 32 + ni * 8 + q * 2;
            float2 xa = *(const float2*)(x0 + col);
            float2 xb = *(const float2*)(x1 + col);
            float2 u, v2_;
            u.x   = fmaxf(fmaf(acc[mi][ni][0], sA, hA) + xa.x, 0.f);
            u.y   = fmaxf(fmaf(acc[mi][ni][1], sA, hA) + xa.y, 0.f);
            v2_.x = fmaxf(fmaf(acc[mi][ni][2], sB, hB) + xb.x, 0.f);
            v2_.y = fmaxf(fmaf(acc[mi][ni][3], sB, hB) + xb.y, 0.f);
            *(float2*)(p0 + col) = u;
            *(float2*)(p1 + col) = v2_;
        }
    }
}

// ---------------- launcher ----------------
extern "C" void kernel_launch(void* const* d_in, const int* in_sizes, int n_in,
                              void* d_out, int out_size)
{
    const float* x  = (const float*)d_in[0];
    const float* wt = (const float*)d_in[1];
    const float* wp = (const float*)d_in[2];
    const float* wg = (const float*)d_in[3];
    const float* wz = (const float*)d_in[4];
    const float* p[16];
    for (int i = 0; i < 16; i++) p[i] = (const float*)d_in[5 + i];
    float* out = (float*)d_out;

    qkv_tc<<<dim3(3, SP / 128, NB), 256>>>(x, wt, wp, wg,
        p[0], p[1], p[2], p[3], p[4], p[5], p[6], p[7], p[8], p[9], p[10], p[11]);

    kv_tc<<<dim3(KVS, NB), 256>>>();
    kv_reduce<<<(NB * WD * WD) / 256, 256>>>();

    outc_tc<<<dim3(SP / 128, NB), 256>>>();

    zeta_tc<<<dim3(CIN / 128, SP / 128, NB), 256>>>(x, wz, p[12], p[13], p[14], p[15], out);
}

// round 13
// speedup vs baseline: 1.3797x; 1.3797x over previous
#include <cuda_runtime.h>
#include <cuda_bf16.h>
#include <cstdint>
#include <cstddef>

#define NB   16
#define CIN  256
#define WD   128
#define SP   4096
#define KVS  16
#define EPSN 1e-5f
#define KC   32     // k-chunk in floats
#define ROWW 36     // SMEM words/row: 16 hi + 16 lo + 4 pad

// ---------------- scratch ----------------
__device__ float g_thetaT[(size_t)NB * SP * WD];
__device__ float g_phi   [(size_t)NB * WD * SP];
__device__ float g_gm    [(size_t)NB * WD * SP];
__device__ float g_kvp   [(size_t)NB * KVS * WD * WD];
__device__ float g_kvT   [(size_t)NB * WD * WD];
__device__ float g_y     [(size_t)NB * SP * WD];

#define MMA_BF16(d, a0,a1,a2,a3, b0,b1) \
    asm volatile("mma.sync.aligned.m16n8k16.row.col.f32.bf16.bf16.f32 " \
        "{%0,%1,%2,%3}, {%4,%5,%6,%7}, {%8,%9}, {%0,%1,%2,%3};" \
        : "+f"((d)[0]), "+f"((d)[1]), "+f"((d)[2]), "+f"((d)[3]) \
        : "r"(a0), "r"(a1), "r"(a2), "r"(a3), "r"(b0), "r"(b1))

__device__ __forceinline__ void cvt_hl(float a, float b, uint32_t& hi, uint32_t& lo) {
    __nv_bfloat16 ha = __float2bfloat16_rn(a), hb = __float2bfloat16_rn(b);
    float fa = __bfloat162float(ha), fb = __bfloat162float(hb);
    __nv_bfloat16 la = __float2bfloat16_rn(a - fa), lb = __float2bfloat16_rn(b - fb);
    __nv_bfloat162 h; h.x = ha; h.y = hb;
    __nv_bfloat162 l; l.x = la; l.y = lb;
    hi = *reinterpret_cast<uint32_t*>(&h);
    lo = *reinterpret_cast<uint32_t*>(&l);
}

// K-major source: 128 rows (m) x 32 floats (k), row stride ldk
__device__ __forceinline__ void load_conv(uint32_t* sm, const float* __restrict__ src,
                                          int ldk, int tid) {
#pragma unroll
    for (int i = 0; i < 4; i++) {
        int f = tid + (i << 8);
        int row = f >> 3, c = f & 7;
        float4 v = *(const float4*)(src + (size_t)row * ldk + (c << 2));
        uint32_t h0, l0, h1, l1;
        cvt_hl(v.x, v.y, h0, l0);
        cvt_hl(v.z, v.w, h1, l1);
        uint32_t* p = sm + row * ROWW + c * 2;
        p[0] = h0; p[1] = h1;
        p[16] = l0; p[17] = l1;
    }
}

// M-major (transposed) source: 32 rows (k) x 128 floats (m), row stride ldm.
// Conflict-free remap: each thread owns one m-row and one 4-word k-group
// (8 k-values read down the column), stored as a single uint4 hi + uint4 lo.
// Gmem: each of the 8 reads is a fully-coalesced 128B row per warp.
// Smem: per-lane byte stride 144, 16B stores -> all 32 banks per quarter-phase.
__device__ __forceinline__ void load_conv_T(uint32_t* sm, const float* __restrict__ src,
                                            int ldm, int tid) {
    const int m = tid & 127;
#pragma unroll
    for (int i = 0; i < 2; i++) {
        int g = (tid >> 7) + 2 * i;                   // k-group 0..3
        const float* p = src + (size_t)(8 * g) * ldm + m;
        float v[8];
#pragma unroll
        for (int j = 0; j < 8; j++) v[j] = p[(size_t)j * ldm];
        uint32_t h[4], l[4];
#pragma unroll
        for (int j = 0; j < 4; j++) cvt_hl(v[2 * j], v[2 * j + 1], h[j], l[j]);
        uint32_t* q = sm + m * ROWW + g * 4;
        *(uint4*)(q)      = make_uint4(h[0], h[1], h[2], h[3]);
        *(uint4*)(q + 16) = make_uint4(l[0], l[1], l[2], l[3]);
    }
}

// D[128][128] = A[128][K] . B[128][K]^T, 3-product bf16 error compensation.
// TA/TB: operand source is [k][m] (transposed in SMEM loader).
template<bool TA, bool TB>
__device__ __forceinline__ void gemm_main(const float* __restrict__ A, int lda,
                                          const float* __restrict__ B, int ldb,
                                          int nchunk, float acc[4][4][4]) {
    __shared__ uint32_t smA[128 * ROWW];
    __shared__ uint32_t smB[128 * ROWW];
    const int tid = threadIdx.x, lane = tid & 31, wid = tid >> 5;
    const int wr = wid >> 2, wc = wid & 3;
    const int r = lane >> 2, q = lane & 3;
#pragma unroll
    for (int mi = 0; mi < 4; mi++)
#pragma unroll
        for (int ni = 0; ni < 4; ni++)
#pragma unroll
            for (int k = 0; k < 4; k++) acc[mi][ni][k] = 0.f;

    for (int kc = 0; kc < nchunk; kc++) {
        if (TA) load_conv_T(smA, A + (size_t)kc * KC * lda, lda, tid);
        else    load_conv  (smA, A + kc * KC, lda, tid);
        if (TB) load_conv_T(smB, B + (size_t)kc * KC * ldb, ldb, tid);
        else    load_conv  (smB, B + kc * KC, ldb, tid);
        __syncthreads();
#pragma unroll
        for (int p = 0; p < 3; p++) {
            const int aoff = (p == 1) ? 16 : 0;
            const int boff = (p == 2) ? 16 : 0;
#pragma unroll
            for (int k2 = 0; k2 < 2; k2++) {
                const int kwA = aoff + k2 * 8, kwB = boff + k2 * 8;
                uint32_t bf[4][2];
#pragma unroll
                for (int ni = 0; ni < 4; ni++) {
                    int nr = wc * 32 + ni * 8 + r;
                    bf[ni][0] = smB[nr * ROWW + kwB + q];
                    bf[ni][1] = smB[nr * ROWW + kwB + 4 + q];
                }
#pragma unroll
                for (int mi = 0; mi < 4; mi++) {
                    int mr = wr * 64 + mi * 16 + r;
                    uint32_t a0 = smA[mr * ROWW + kwA + q];
                    uint32_t a1 = smA[(mr + 8) * ROWW + kwA + q];
                    uint32_t a2 = smA[mr * ROWW + kwA + 4 + q];
                    uint32_t a3 = smA[(mr + 8) * ROWW + kwA + 4 + q];
#pragma unroll
                    for (int ni = 0; ni < 4; ni++)
                        MMA_BF16(acc[mi][ni], a0, a1, a2, a3, bf[ni][0], bf[ni][1]);
                }
            }
        }
        __syncthreads();
    }
}

// ---------------- GEMM 1: theta/phi/g ----------------
// grid (3, SP/128, NB): proj fastest -> x tile L2 reuse across projs
__global__ __launch_bounds__(256, 2) void qkv_tc(
    const float* __restrict__ x,
    const float* __restrict__ w0, const float* __restrict__ w1, const float* __restrict__ w2,
    const float* __restrict__ g1, const float* __restrict__ b1, const float* __restrict__ m1, const float* __restrict__ v1,
    const float* __restrict__ g2, const float* __restrict__ b2, const float* __restrict__ m2, const float* __restrict__ v2,
    const float* __restrict__ g3, const float* __restrict__ b3, const float* __restrict__ m3, const float* __restrict__ v3)
{
    const int proj = blockIdx.x, n = blockIdx.z, s0 = blockIdx.y * 128;
    const float* w = (proj == 0) ? w0 : (proj == 1) ? w1 : w2;
    const float* xsrc = x + (size_t)n * CIN * SP + s0;   // element (k=0, m=s0), row stride SP
    float acc[4][4][4];
    if (proj == 0) gemm_main<true,  false>(xsrc, SP, w, CIN, CIN / KC, acc);  // D[s][c']
    else           gemm_main<false, true >(w, CIN, xsrc, SP, CIN / KC, acc);  // D[c'][s]

    const int lane = threadIdx.x & 31, wid = threadIdx.x >> 5;
    const int wr = wid >> 2, wc = wid & 3, r = lane >> 2, q = lane & 3;

    if (proj == 0) {    // BN per column c'
#pragma unroll
        for (int mi = 0; mi < 4; mi++) {
            int sr = wr * 64 + mi * 16 + r;
            float* d0 = g_thetaT + ((size_t)n * SP + s0 + sr) * WD;
            float* d1 = d0 + (size_t)8 * WD;
#pragma unroll
            for (int ni = 0; ni < 4; ni++) {
                int col = wc * 32 + ni * 8 + q * 2;
                float sa = g1[col] * rsqrtf(v1[col] + EPSN);
                float ha = b1[col] - m1[col] * sa;
                float sb = g1[col + 1] * rsqrtf(v1[col + 1] + EPSN);
                float hb = b1[col + 1] - m1[col + 1] * sb;
                float2 u, v2_;
                u.x   = fmaxf(fmaf(acc[mi][ni][0], sa, ha), 0.f);
                u.y   = fmaxf(fmaf(acc[mi][ni][1], sb, hb), 0.f);
                v2_.x = fmaxf(fmaf(acc[mi][ni][2], sa, ha), 0.f);
                v2_.y = fmaxf(fmaf(acc[mi][ni][3], sb, hb), 0.f);
                *(float2*)(d0 + col) = u;
                *(float2*)(d1 + col) = v2_;
            }
        }
    } else {            // BN per row c'
        const float* bg = (proj == 1) ? g2 : g3; const float* bb = (proj == 1) ? b2 : b3;
        const float* bm = (proj == 1) ? m2 : m3; const float* bv = (proj == 1) ? v2 : v3;
        float* dst = (proj == 1) ? g_phi : g_gm;
#pragma unroll
        for (int mi = 0; mi < 4; mi++) {
            int c0r = wr * 64 + mi * 16 + r, c1r = c0r + 8;
            float sA = bg[c0r] * rsqrtf(bv[c0r] + EPSN), hA = bb[c0r] - bm[c0r] * sA;
            float sB = bg[c1r] * rsqrtf(bv[c1r] + EPSN), hB = bb[c1r] - bm[c1r] * sB;
            float* p0 = dst + ((size_t)n * WD + c0r) * SP + s0;
            float* p1 = dst + ((size_t)n * WD + c1r) * SP + s0;
#pragma unroll
            for (int ni = 0; ni < 4; ni++) {
                int col = wc * 32 + ni * 8 + q * 2;
                float2 u, v2_;
                u.x   = fmaxf(fmaf(acc[mi][ni][0], sA, hA), 0.f);
                u.y   = fmaxf(fmaf(acc[mi][ni][1], sA, hA), 0.f);
                v2_.x = fmaxf(fmaf(acc[mi][ni][2], sB, hB), 0.f);
                v2_.y = fmaxf(fmaf(acc[mi][ni][3], sB, hB), 0.f);
                *(float2*)(p0 + col) = u;
                *(float2*)(p1 + col) = v2_;
            }
        }
    }
}

// ---------------- GEMM 2: kv partials (D[d][c]) ---------------- grid (KVS, NB)
__global__ __launch_bounds__(256, 2) void kv_tc()
{
    const int n = blockIdx.y, s0 = blockIdx.x * (SP / KVS);
    const float* gsrc = g_gm  + (size_t)n * WD * SP + s0;
    const float* psrc = g_phi + (size_t)n * WD * SP + s0;
    float acc[4][4][4];
    gemm_main<false, false>(gsrc, SP, psrc, SP, (SP / KVS) / KC, acc);

    const int lane = threadIdx.x & 31, wid = threadIdx.x >> 5;
    const int wr = wid >> 2, wc = wid & 3, r = lane >> 2, q = lane & 3;
    float* base = g_kvp + ((size_t)n * KVS + blockIdx.x) * WD * WD;
#pragma unroll
    for (int mi = 0; mi < 4; mi++) {
        int dr = wr * 64 + mi * 16 + r;
        float* p0 = base + (size_t)dr * WD;
        float* p1 = p0 + (size_t)8 * WD;
#pragma unroll
        for (int ni = 0; ni < 4; ni++) {
            int col = wc * 32 + ni * 8 + q * 2;
            *(float2*)(p0 + col) = make_float2(acc[mi][ni][0], acc[mi][ni][1]);
            *(float2*)(p1 + col) = make_float2(acc[mi][ni][2], acc[mi][ni][3]);
        }
    }
}
__global__ __launch_bounds__(256) void kv_reduce()
{
    int idx = blockIdx.x * 256 + threadIdx.x;
    int n = idx >> 14, dc = idx & 16383;
    float s = 0.f;
#pragma unroll
    for (int k = 0; k < KVS; k++) s += g_kvp[(((size_t)n * KVS + k) << 14) + dc];
    g_kvT[idx] = s;
}

// ---------------- GEMM 3: y_flat (D[s][d]) ---------------- grid (SP/128, NB)
__global__ __launch_bounds__(256, 2) void outc_tc()
{
    const int n = blockIdx.y, s0 = blockIdx.x * 128;
    const float* tsrc = g_thetaT + ((size_t)n * SP + s0) * WD;
    const float* ksrc = g_kvT + (size_t)n * WD * WD;
    float acc[4][4][4];
    gemm_main<false, false>(tsrc, WD, ksrc, WD, WD / KC, acc);

    const int lane = threadIdx.x & 31, wid = threadIdx.x >> 5;
    const int wr = wid >> 2, wc = wid & 3, r = lane >> 2, q = lane & 3;
#pragma unroll
    for (int mi = 0; mi < 4; mi++) {
        int sr = wr * 64 + mi * 16 + r;
        float* p0 = g_y + ((size_t)n * SP + s0 + sr) * WD;
        float* p1 = p0 + (size_t)8 * WD;
#pragma unroll
        for (int ni = 0; ni < 4; ni++) {
            int col = wc * 32 + ni * 8 + q * 2;
            *(float2*)(p0 + col) = make_float2(acc[mi][ni][0], acc[mi][ni][1]);
            *(float2*)(p1 + col) = make_float2(acc[mi][ni][2], acc[mi][ni][3]);
        }
    }
}

// ---------------- GEMM 4: zeta + BN4 + residual + relu (D[o][s]) ----------------
// grid (CIN/128, SP/128, NB): o-tile fastest -> y tile L2 reuse.
// B operand: y viewed as [w][sp] (flat w*4096+sp), rows contiguous in sp -> transposed loader.
__global__ __launch_bounds__(256, 2) void zeta_tc(
    const float* __restrict__ x, const float* __restrict__ wz,
    const float* __restrict__ g4, const float* __restrict__ b4,
    const float* __restrict__ m4, const float* __restrict__ v4,
    float* __restrict__ out)
{
    const int n = blockIdx.z, o0 = blockIdx.x * 128, s0 = blockIdx.y * 128;
    const float* wsrc = wz + (size_t)o0 * WD;
    const float* ysrc = g_y + (size_t)n * SP * WD + s0;   // element (k=w=0, m=sp=s0), row stride SP
    float acc[4][4][4];
    gemm_main<false, true>(wsrc, WD, ysrc, SP, WD / KC, acc);

    const int lane = threadIdx.x & 31, wid = threadIdx.x >> 5;
    const int wr = wid >> 2, wc = wid & 3, r = lane >> 2, q = lane & 3;
#pragma unroll
    for (int mi = 0; mi < 4; mi++) {
        int oA = o0 + wr * 64 + mi * 16 + r, oB = oA + 8;
        float sA = g4[oA] * rsqrtf(v4[oA] + EPSN), hA = b4[oA] - m4[oA] * sA;
        float sB = g4[oB] * rsqrtf(v4[oB] + EPSN), hB = b4[oB] - m4[oB] * sB;
        const float* x0 = x + ((size_t)n * CIN + oA) * SP + s0;
        const float* x1 = x + ((size_t)n * CIN + oB) * SP + s0;
        float* p0 = out + ((size_t)n * CIN + oA) * SP + s0;
        float* p1 = out + ((size_t)n * CIN + oB) * SP + s0;
#pragma unroll
        for (int ni = 0; ni < 4; ni++) {
            int col = wc * 32 + ni * 8 + q * 2;
            float2 xa = *(const float2*)(x0 + col);
            float2 xb = *(const float2*)(x1 + col);
            float2 u, v2_;
            u.x   = fmaxf(fmaf(acc[mi][ni][0], sA, hA) + xa.x, 0.f);
            u.y   = fmaxf(fmaf(acc[mi][ni][1], sA, hA) + xa.y, 0.f);
            v2_.x = fmaxf(fmaf(acc[mi][ni][2], sB, hB) + xb.x, 0.f);
            v2_.y = fmaxf(fmaf(acc[mi][ni][3], sB, hB) + xb.y, 0.f);
            *(float2*)(p0 + col) = u;
            *(float2*)(p1 + col) = v2_;
        }
    }
}

// ---------------- launcher ----------------
extern "C" void kernel_launch(void* const* d_in, const int* in_sizes, int n_in,
                              void* d_out, int out_size)
{
    const float* x  = (const float*)d_in[0];
    const float* wt = (const float*)d_in[1];
    const float* wp = (const float*)d_in[2];
    const float* wg = (const float*)d_in[3];
    const float* wz = (const float*)d_in[4];
    const float* p[16];
    for (int i = 0; i < 16; i++) p[i] = (const float*)d_in[5 + i];
    float* out = (float*)d_out;

    qkv_tc<<<dim3(3, SP / 128, NB), 256>>>(x, wt, wp, wg,
        p[0], p[1], p[2], p[3], p[4], p[5], p[6], p[7], p[8], p[9], p[10], p[11]);

    kv_tc<<<dim3(KVS, NB), 256>>>();
    kv_reduce<<<(NB * WD * WD) / 256, 256>>>();

    outc_tc<<<dim3(SP / 128, NB), 256>>>();

    zeta_tc<<<dim3(CIN / 128, SP / 128, NB), 256>>>(x, wz, p[12], p[13], p[14], p[15], out);
}

// round 15
// speedup vs baseline: 1.4125x; 1.0238x over previous
#include <cuda_runtime.h>
#include <cuda_bf16.h>
#include <cstdint>
#include <cstddef>

#define NB   16
#define CIN  256
#define WD   128
#define SP   4096
#define KVS  16
#define EPSN 1e-5f
#define KC   32     // k-chunk in floats
#define ROWW 36     // SMEM words/row: 16 hi + 16 lo + 4 pad
#define TILE (128 * ROWW)            // words per operand tile
#define SMEM_BYTES (4 * TILE * 4)    // A0,B0,A1,B1

// ---------------- scratch ----------------
__device__ float g_thetaT[(size_t)NB * SP * WD];
__device__ float g_phi   [(size_t)NB * WD * SP];
__device__ float g_gm    [(size_t)NB * WD * SP];
__device__ float g_kvp   [(size_t)NB * KVS * WD * WD];
__device__ float g_kvT   [(size_t)NB * WD * WD];
__device__ float g_y     [(size_t)NB * SP * WD];

#define MMA_BF16(d, a0,a1,a2,a3, b0,b1) \
    asm volatile("mma.sync.aligned.m16n8k16.row.col.f32.bf16.bf16.f32 " \
        "{%0,%1,%2,%3}, {%4,%5,%6,%7}, {%8,%9}, {%0,%1,%2,%3};" \
        : "+f"((d)[0]), "+f"((d)[1]), "+f"((d)[2]), "+f"((d)[3]) \
        : "r"(a0), "r"(a1), "r"(a2), "r"(a3), "r"(b0), "r"(b1))

// Truncation split: hi = exact top-16-bit bf16 (1 PRMT to pack the pair),
// lo = rn(a - hi). Dropped Al*Bl <= 2^-16 rel, same bound as before.
__device__ __forceinline__ void cvt_hl(float a, float b, uint32_t& hi, uint32_t& lo) {
    uint32_t ua = __float_as_uint(a), ub = __float_as_uint(b);
    hi = __byte_perm(ua, ub, 0x7632);
    float la = a - __uint_as_float(ua & 0xFFFF0000u);
    float lb = b - __uint_as_float(ub & 0xFFFF0000u);
    asm("cvt.rn.bf16x2.f32 %0, %1, %2;" : "=r"(lo) : "f"(lb), "f"(la));
}

// K-major source: 128 rows (m) x 32 floats (k), row stride ldk
__device__ __forceinline__ void load_conv(uint32_t* sm, const float* __restrict__ src,
                                          int ldk, int tid) {
#pragma unroll
    for (int i = 0; i < 4; i++) {
        int f = tid + (i << 8);
        int row = f >> 3, c = f & 7;
        float4 v = *(const float4*)(src + (size_t)row * ldk + (c << 2));
        uint32_t h0, l0, h1, l1;
        cvt_hl(v.x, v.y, h0, l0);
        cvt_hl(v.z, v.w, h1, l1);
        uint32_t* p = sm + row * ROWW + c * 2;
        p[0] = h0; p[1] = h1;
        p[16] = l0; p[17] = l1;
    }
}

// M-major (transposed) source: 32 rows (k) x 128 floats (m), row stride ldm.
// Conflict-free: thread owns one m-row + one 4-word k-group; uint4 stores
// span all 32 banks per 8-lane phase (stride 144B).
__device__ __forceinline__ void load_conv_T(uint32_t* sm, const float* __restrict__ src,
                                            int ldm, int tid) {
    const int m = tid & 127;
#pragma unroll
    for (int i = 0; i < 2; i++) {
        int g = (tid >> 7) + 2 * i;                   // k-group 0..3
        const float* p = src + (size_t)(8 * g) * ldm + m;
        float v[8];
#pragma unroll
        for (int j = 0; j < 8; j++) v[j] = p[(size_t)j * ldm];
        uint32_t h[4], l[4];
#pragma unroll
        for (int j = 0; j < 4; j++) cvt_hl(v[2 * j], v[2 * j + 1], h[j], l[j]);
        uint32_t* q = sm + m * ROWW + g * 4;
        *(uint4*)(q)      = make_uint4(h[0], h[1], h[2], h[3]);
        *(uint4*)(q + 16) = make_uint4(l[0], l[1], l[2], l[3]);
    }
}

// One chunk of MMAs: 3 compensation passes x 2 k-steps over the 128x128 tile.
__device__ __forceinline__ void mma_tile(const uint32_t* smA, const uint32_t* smB,
                                         float acc[4][4][4], int lane, int wid) {
    const int wr = wid >> 2, wc = wid & 3;
    const int r = lane >> 2, q = lane & 3;
#pragma unroll
    for (int p = 0; p < 3; p++) {
        const int aoff = (p == 1) ? 16 : 0;
        const int boff = (p == 2) ? 16 : 0;
#pragma unroll
        for (int k2 = 0; k2 < 2; k2++) {
            const int kwA = aoff + k2 * 8, kwB = boff + k2 * 8;
            uint32_t bf[4][2];
#pragma unroll
            for (int ni = 0; ni < 4; ni++) {
                int nr = wc * 32 + ni * 8 + r;
                bf[ni][0] = smB[nr * ROWW + kwB + q];
                bf[ni][1] = smB[nr * ROWW + kwB + 4 + q];
            }
#pragma unroll
            for (int mi = 0; mi < 4; mi++) {
                int mr = wr * 64 + mi * 16 + r;
                uint32_t a0 = smA[mr * ROWW + kwA + q];
                uint32_t a1 = smA[(mr + 8) * ROWW + kwA + q];
                uint32_t a2 = smA[mr * ROWW + kwA + 4 + q];
                uint32_t a3 = smA[(mr + 8) * ROWW + kwA + 4 + q];
#pragma unroll
                for (int ni = 0; ni < 4; ni++)
                    MMA_BF16(acc[mi][ni], a0, a1, a2, a3, bf[ni][0], bf[ni][1]);
            }
        }
    }
}

// D[128][128] = A[128][K].B[128][K]^T, bf16 3-product compensation,
// double-buffered SMEM pipeline: MMA(cur) overlaps load(nxt), 1 barrier/chunk.
template<bool TA, bool TB>
__device__ __forceinline__ void gemm_main(const float* __restrict__ A, int lda,
                                          const float* __restrict__ B, int ldb,
                                          int nchunk, float acc[4][4][4]) {
    extern __shared__ uint32_t dsm[];
    const int tid = threadIdx.x, lane = tid & 31, wid = tid >> 5;
#pragma unroll
    for (int mi = 0; mi < 4; mi++)
#pragma unroll
        for (int ni = 0; ni < 4; ni++)
#pragma unroll
            for (int k = 0; k < 4; k++) acc[mi][ni][k] = 0.f;

    // buffers: A0 B0 A1 B1
    if (TA) load_conv_T(dsm, A, lda, tid);
    else    load_conv  (dsm, A, lda, tid);
    if (TB) load_conv_T(dsm + TILE, B, ldb, tid);
    else    load_conv  (dsm + TILE, B, ldb, tid);
    __syncthreads();

    for (int kc = 0; kc < nchunk; kc++) {
        const int cur = kc & 1;
        const uint32_t* sA = dsm + (cur ? 2 * TILE : 0);
        const uint32_t* sB = sA + TILE;
        mma_tile(sA, sB, acc, lane, wid);
        if (kc + 1 < nchunk) {
            uint32_t* nA = dsm + (cur ? 0 : 2 * TILE);
            uint32_t* nB = nA + TILE;
            if (TA) load_conv_T(nA, A + (size_t)(kc + 1) * KC * lda, lda, tid);
            else    load_conv  (nA, A + (kc + 1) * KC, lda, tid);
            if (TB) load_conv_T(nB, B + (size_t)(kc + 1) * KC * ldb, ldb, tid);
            else    load_conv  (nB, B + (kc + 1) * KC, ldb, tid);
        }
        __syncthreads();
    }
}

// ---------------- GEMM 1: theta/phi/g ----------------
// grid (3, SP/128, NB): proj fastest -> x tile L2 reuse across projs
__global__ __launch_bounds__(256, 2) void qkv_tc(
    const float* __restrict__ x,
    const float* __restrict__ w0, const float* __restrict__ w1, const float* __restrict__ w2,
    const float* __restrict__ g1, const float* __restrict__ b1, const float* __restrict__ m1, const float* __restrict__ v1,
    const float* __restrict__ g2, const float* __restrict__ b2, const float* __restrict__ m2, const float* __restrict__ v2,
    const float* __restrict__ g3, const float* __restrict__ b3, const float* __restrict__ m3, const float* __restrict__ v3)
{
    const int proj = blockIdx.x, n = blockIdx.z, s0 = blockIdx.y * 128;
    const float* w = (proj == 0) ? w0 : (proj == 1) ? w1 : w2;
    const float* xsrc = x + (size_t)n * CIN * SP + s0;   // (k=0, m=s0), row stride SP
    float acc[4][4][4];
    if (proj == 0) gemm_main<true,  false>(xsrc, SP, w, CIN, CIN / KC, acc);  // D[s][c']
    else           gemm_main<false, true >(w, CIN, xsrc, SP, CIN / KC, acc);  // D[c'][s]

    const int lane = threadIdx.x & 31, wid = threadIdx.x >> 5;
    const int wr = wid >> 2, wc = wid & 3, r = lane >> 2, q = lane & 3;

    if (proj == 0) {    // BN per column c'
#pragma unroll
        for (int mi = 0; mi < 4; mi++) {
            int sr = wr * 64 + mi * 16 + r;
            float* d0 = g_thetaT + ((size_t)n * SP + s0 + sr) * WD;
            float* d1 = d0 + (size_t)8 * WD;
#pragma unroll
            for (int ni = 0; ni < 4; ni++) {
                int col = wc * 32 + ni * 8 + q * 2;
                float sa = g1[col] * rsqrtf(v1[col] + EPSN);
                float ha = b1[col] - m1[col] * sa;
                float sb = g1[col + 1] * rsqrtf(v1[col + 1] + EPSN);
                float hb = b1[col + 1] - m1[col + 1] * sb;
                float2 u, v2_;
                u.x   = fmaxf(fmaf(acc[mi][ni][0], sa, ha), 0.f);
                u.y   = fmaxf(fmaf(acc[mi][ni][1], sb, hb), 0.f);
                v2_.x = fmaxf(fmaf(acc[mi][ni][2], sa, ha), 0.f);
                v2_.y = fmaxf(fmaf(acc[mi][ni][3], sb, hb), 0.f);
                *(float2*)(d0 + col) = u;
                *(float2*)(d1 + col) = v2_;
            }
        }
    } else {            // BN per row c'
        const float* bg = (proj == 1) ? g2 : g3; const float* bb = (proj == 1) ? b2 : b3;
        const float* bm = (proj == 1) ? m2 : m3; const float* bv = (proj == 1) ? v2 : v3;
        float* dst = (proj == 1) ? g_phi : g_gm;
#pragma unroll
        for (int mi = 0; mi < 4; mi++) {
            int c0r = wr * 64 + mi * 16 + r, c1r = c0r + 8;
            float sA = bg[c0r] * rsqrtf(bv[c0r] + EPSN), hA = bb[c0r] - bm[c0r] * sA;
            float sB = bg[c1r] * rsqrtf(bv[c1r] + EPSN), hB = bb[c1r] - bm[c1r] * sB;
            float* p0 = dst + ((size_t)n * WD + c0r) * SP + s0;
            float* p1 = dst + ((size_t)n * WD + c1r) * SP + s0;
#pragma unroll
            for (int ni = 0; ni < 4; ni++) {
                int col = wc * 32 + ni * 8 + q * 2;
                float2 u, v2_;
                u.x   = fmaxf(fmaf(acc[mi][ni][0], sA, hA), 0.f);
                u.y   = fmaxf(fmaf(acc[mi][ni][1], sA, hA), 0.f);
                v2_.x = fmaxf(fmaf(acc[mi][ni][2], sB, hB), 0.f);
                v2_.y = fmaxf(fmaf(acc[mi][ni][3], sB, hB), 0.f);
                *(float2*)(p0 + col) = u;
                *(float2*)(p1 + col) = v2_;
            }
        }
    }
}

// ---------------- GEMM 2: kv partials (D[d][c]) ---------------- grid (KVS, NB)
__global__ __launch_bounds__(256, 2) void kv_tc()
{
    const int n = blockIdx.y, s0 = blockIdx.x * (SP / KVS);
    const float* gsrc = g_gm  + (size_t)n * WD * SP + s0;
    const float* psrc = g_phi + (size_t)n * WD * SP + s0;
    float acc[4][4][4];
    gemm_main<false, false>(gsrc, SP, psrc, SP, (SP / KVS) / KC, acc);

    const int lane = threadIdx.x & 31, wid = threadIdx.x >> 5;
    const int wr = wid >> 2, wc = wid & 3, r = lane >> 2, q = lane & 3;
    float* base = g_kvp + ((size_t)n * KVS + blockIdx.x) * WD * WD;
#pragma unroll
    for (int mi = 0; mi < 4; mi++) {
        int dr = wr * 64 + mi * 16 + r;
        float* p0 = base + (size_t)dr * WD;
        float* p1 = p0 + (size_t)8 * WD;
#pragma unroll
        for (int ni = 0; ni < 4; ni++) {
            int col = wc * 32 + ni * 8 + q * 2;
            *(float2*)(p0 + col) = make_float2(acc[mi][ni][0], acc[mi][ni][1]);
            *(float2*)(p1 + col) = make_float2(acc[mi][ni][2], acc[mi][ni][3]);
        }
    }
}
__global__ __launch_bounds__(256) void kv_reduce()
{
    int idx = blockIdx.x * 256 + threadIdx.x;
    int n = idx >> 14, dc = idx & 16383;
    float s = 0.f;
#pragma unroll
    for (int k = 0; k < KVS; k++) s += g_kvp[(((size_t)n * KVS + k) << 14) + dc];
    g_kvT[idx] = s;
}

// ---------------- GEMM 3: y_flat (D[s][d]) ---------------- grid (SP/128, NB)
__global__ __launch_bounds__(256, 2) void outc_tc()
{
    const int n = blockIdx.y, s0 = blockIdx.x * 128;
    const float* tsrc = g_thetaT + ((size_t)n * SP + s0) * WD;
    const float* ksrc = g_kvT + (size_t)n * WD * WD;
    float acc[4][4][4];
    gemm_main<false, false>(tsrc, WD, ksrc, WD, WD / KC, acc);

    const int lane = threadIdx.x & 31, wid = threadIdx.x >> 5;
    const int wr = wid >> 2, wc = wid & 3, r = lane >> 2, q = lane & 3;
#pragma unroll
    for (int mi = 0; mi < 4; mi++) {
        int sr = wr * 64 + mi * 16 + r;
        float* p0 = g_y + ((size_t)n * SP + s0 + sr) * WD;
        float* p1 = p0 + (size_t)8 * WD;
#pragma unroll
        for (int ni = 0; ni < 4; ni++) {
            int col = wc * 32 + ni * 8 + q * 2;
            *(float2*)(p0 + col) = make_float2(acc[mi][ni][0], acc[mi][ni][1]);
            *(float2*)(p1 + col) = make_float2(acc[mi][ni][2], acc[mi][ni][3]);
        }
    }
}

// ---------------- GEMM 4: zeta + BN4 + residual + relu (D[o][s]) ----------------
// grid (CIN/128, SP/128, NB): o-tile fastest -> y tile L2 reuse.
__global__ __launch_bounds__(256, 2) void zeta_tc(
    const float* __restrict__ x, const float* __restrict__ wz,
    const float* __restrict__ g4, const float* __restrict__ b4,
    const float* __restrict__ m4, const float* __restrict__ v4,
    float* __restrict__ out)
{
    const int n = blockIdx.z, o0 = blockIdx.x * 128, s0 = blockIdx.y * 128;
    const float* wsrc = wz + (size_t)o0 * WD;
    const float* ysrc = g_y + (size_t)n * SP * WD + s0;   // y as [w][sp], row stride SP
    float acc[4][4][4];
    gemm_main<false, true>(wsrc, WD, ysrc, SP, WD / KC, acc);

    const int lane = threadIdx.x & 31, wid = threadIdx.x >> 5;
    const int wr = wid >> 2, wc = wid & 3, r = lane >> 2, q = lane & 3;
#pragma unroll
    for (int mi = 0; mi < 4; mi++) {
        int oA = o0 + wr * 64 + mi * 16 + r, oB = oA + 8;
        float sA = g4[oA] * rsqrtf(v4[oA] + EPSN), hA = b4[oA] - m4[oA] * sA;
        float sB = g4[oB] * rsqrtf(v4[oB] + EPSN), hB = b4[oB] - m4[oB] * sB;
        const float* x0 = x + ((size_t)n * CIN + oA) * SP + s0;
        const float* x1 = x + ((size_t)n * CIN + oB) * SP + s0;
        float* p0 = out + ((size_t)n * CIN + oA) * SP + s0;
        float* p1 = out + ((size_t)n * CIN + oB) * SP + s0;
#pragma unroll
        for (int ni = 0; ni < 4; ni++) {
            int col = wc * 32 + ni * 8 + q * 2;
            float2 xa = *(const float2*)(x0 + col);
            float2 xb = *(const float2*)(x1 + col);
            float2 u, v2_;
            u.x   = fmaxf(fmaf(acc[mi][ni][0], sA, hA) + xa.x, 0.f);
            u.y   = fmaxf(fmaf(acc[mi][ni][1], sA, hA) + xa.y, 0.f);
            v2_.x = fmaxf(fmaf(acc[mi][ni][2], sB, hB) + xb.x, 0.f);
            v2_.y = fmaxf(fmaf(acc[mi][ni][3], sB, hB) + xb.y, 0.f);
            *(float2*)(p0 + col) = u;
            *(float2*)(p1 + col) = v2_;
        }
    }
}

// ---------------- launcher ----------------
extern "C" void kernel_launch(void* const* d_in, const int* in_sizes, int n_in,
                              void* d_out, int out_size)
{
    const float* x  = (const float*)d_in[0];
    const float* wt = (const float*)d_in[1];
    const float* wp = (const float*)d_in[2];
    const float* wg = (const float*)d_in[3];
    const float* wz = (const float*)d_in[4];
    const float* p[16];
    for (int i = 0; i < 16; i++) p[i] = (const float*)d_in[5 + i];
    float* out = (float*)d_out;

    cudaFuncSetAttribute(qkv_tc,  cudaFuncAttributeMaxDynamicSharedMemorySize, SMEM_BYTES);
    cudaFuncSetAttribute(kv_tc,   cudaFuncAttributeMaxDynamicSharedMemorySize, SMEM_BYTES);
    cudaFuncSetAttribute(outc_tc, cudaFuncAttributeMaxDynamicSharedMemorySize, SMEM_BYTES);
    cudaFuncSetAttribute(zeta_tc, cudaFuncAttributeMaxDynamicSharedMemorySize, SMEM_BYTES);

    qkv_tc<<<dim3(3, SP / 128, NB), 256, SMEM_BYTES>>>(x, wt, wp, wg,
        p[0], p[1], p[2], p[3], p[4], p[5], p[6], p[7], p[8], p[9], p[10], p[11]);

    kv_tc<<<dim3(KVS, NB), 256, SMEM_BYTES>>>();
    kv_reduce<<<(NB * WD * WD) / 256, 256>>>();

    outc_tc<<<dim3(SP / 128, NB), 256, SMEM_BYTES>>>();

    zeta_tc<<<dim3(CIN / 128, SP / 128, NB), 256, SMEM_BYTES>>>(x, wz, p[12], p[13], p[14], p[15], out);
}